// round 13
// baseline (speedup 1.0000x reference)
#include <cuda_runtime.h>
#include <cuda.h>
#include <stdint.h>
#include <math.h>

#define B_ 8
#define T_ 2048
#define D_ 768
#define KC 32
#define LDS_ 36                         // padded row stride (floats)
#define TA_FLOATS (64 * LDS_)           // 2304 floats: A tile (64 rows)
#define TB_FLOATS (128 * LDS_)          // 4608 floats: B tile (128 rows)
#define STAGE_FLOATS (TA_FLOATS + TB_FLOATS)
#define SMEM_DYN (2 * STAGE_FLOATS * 4) // 2 stages = 55296 B

// Scratch: raw scaled scores; transposed tf32 X; converted row-major X; row stats.
__device__ float g_S[(size_t)B_ * T_ * T_];
__device__ float g_Xt[(size_t)B_ * D_ * T_];
__device__ float g_Xc[(size_t)B_ * T_ * D_];
__device__ float2 g_stat[(size_t)B_ * T_];   // (rowmax, 1/sumexp); (0,0) if row masked

__device__ __forceinline__ uint32_t f2tf32(float v) {
    uint32_t o;
    asm("cvt.rna.tf32.f32 %0, %1;" : "=r"(o) : "f"(v));
    return o;
}

__device__ __forceinline__ void mma_tf32(float& c0, float& c1, float& c2, float& c3,
                                         uint32_t a0, uint32_t a1, uint32_t a2, uint32_t a3,
                                         uint32_t b0, uint32_t b1) {
    asm volatile(
        "mma.sync.aligned.m16n8k8.row.col.f32.tf32.tf32.f32 "
        "{%0,%1,%2,%3}, {%4,%5,%6,%7}, {%8,%9}, {%0,%1,%2,%3};"
        : "+f"(c0), "+f"(c1), "+f"(c2), "+f"(c3)
        : "r"(a0), "r"(a1), "r"(a2), "r"(a3), "r"(b0), "r"(b1));
}

__device__ __forceinline__ void ldsm_x4(uint32_t& r0, uint32_t& r1, uint32_t& r2,
                                        uint32_t& r3, uint32_t addr) {
    asm volatile("ldmatrix.sync.aligned.m8n8.x4.shared.b16 {%0,%1,%2,%3}, [%4];"
                 : "=r"(r0), "=r"(r1), "=r"(r2), "=r"(r3) : "r"(addr));
}

struct Frag { float c[2][8][4]; };
struct FragAddr { uint32_t a0, a1, b0, b1, b2, b3; };

__device__ __forceinline__ FragAddr make_addr() {
    int tid = threadIdx.x, wid = tid >> 5, lane = tid & 31;
    int wr = (wid >> 1) * 32;
    int wc = (wid & 1) * 64;
    FragAddr fa;
    uint32_t arow = (uint32_t)(wr + (lane & 7) + ((lane >> 3) & 1) * 8);
    uint32_t akof = (uint32_t)((lane >> 4) & 1) * 4u;
    fa.a0 = (arow * LDS_ + akof) * 4u;
    fa.a1 = ((arow + 16) * LDS_ + akof) * 4u;
    uint32_t brow = (uint32_t)(wc + ((lane >> 4) & 1) * 8 + (lane & 7));
    uint32_t bkof = (uint32_t)((lane >> 3) & 1) * 4u;
    fa.b0 = ((brow + 0) * LDS_ + bkof) * 4u;
    fa.b1 = ((brow + 16) * LDS_ + bkof) * 4u;
    fa.b2 = ((brow + 32) * LDS_ + bkof) * 4u;
    fa.b3 = ((brow + 48) * LDS_ + bkof) * 4u;
    return fa;
}

__device__ __forceinline__ void compute_ks(uint32_t sA, uint32_t sB, const FragAddr& fa,
                                           int ksIdx, Frag& fr) {
    uint32_t kb = (uint32_t)ksIdx * 32u;
    uint32_t a[2][4];
    uint32_t bb[16];
    ldsm_x4(a[0][0], a[0][1], a[0][2], a[0][3], sA + fa.a0 + kb);
    ldsm_x4(a[1][0], a[1][1], a[1][2], a[1][3], sA + fa.a1 + kb);
    ldsm_x4(bb[0],  bb[1],  bb[2],  bb[3],  sB + fa.b0 + kb);
    ldsm_x4(bb[4],  bb[5],  bb[6],  bb[7],  sB + fa.b1 + kb);
    ldsm_x4(bb[8],  bb[9],  bb[10], bb[11], sB + fa.b2 + kb);
    ldsm_x4(bb[12], bb[13], bb[14], bb[15], sB + fa.b3 + kb);
#pragma unroll
    for (int n = 0; n < 8; n++) {
        uint32_t b0 = bb[(n >> 1) * 4 + (n & 1) * 2];
        uint32_t b1 = bb[(n >> 1) * 4 + (n & 1) * 2 + 1];
#pragma unroll
        for (int m = 0; m < 2; m++)
            mma_tf32(fr.c[m][n][0], fr.c[m][n][1], fr.c[m][n][2], fr.c[m][n][3],
                     a[m][0], a[m][1], a[m][2], a[m][3], b0, b1);
    }
}

// cp.async producer: A chunk (64x32) + B chunk (128x32) into given stage.
__device__ __forceinline__ void issue_chunk(const float* __restrict__ A, int lda,
                                            const float* __restrict__ Bp, int ldb,
                                            int k0, uint32_t sA, uint32_t sB) {
    int tid = threadIdx.x;
    int row = tid >> 3, f4 = tid & 7;
#pragma unroll
    for (int p = 0; p < 4; p++) {
        int r = row + p * 16;
        const float* ga = A + (size_t)r * lda + k0 + f4 * 4;
        uint32_t da = sA + (uint32_t)(r * LDS_ + f4 * 4) * 4u;
        asm volatile("cp.async.cg.shared.global [%0], [%1], 16;" :: "r"(da), "l"(ga));
    }
#pragma unroll
    for (int p = 0; p < 8; p++) {
        int r = row + p * 16;
        const float* gb = Bp + (size_t)r * ldb + k0 + f4 * 4;
        uint32_t db = sB + (uint32_t)(r * LDS_ + f4 * 4) * 4u;
        asm volatile("cp.async.cg.shared.global [%0], [%1], 16;" :: "r"(db), "l"(gb));
    }
    asm volatile("cp.async.commit_group;" ::: "memory");
}

// ---------------------------------------------------------------------------
// Kernel 1: S[b,i,j] = Xc[b,i,:].Xc[b,j,:] / sqrt(D) — raw scores (tiles j0<=i0)
// (R12 mainloop, unchanged)
// ---------------------------------------------------------------------------
__global__ void __launch_bounds__(128, 4) qk_mma_kernel() {
    int b = blockIdx.z;
    int i0 = blockIdx.y * 64;
    int j0 = blockIdx.x * 128;
    if (j0 > i0) return;

    extern __shared__ uint32_t sm[];
    const float* A = g_Xc + (size_t)b * T_ * D_ + (size_t)i0 * D_;
    const float* Bp = g_Xc + (size_t)b * T_ * D_ + (size_t)j0 * D_;

    Frag fr;
#pragma unroll
    for (int m = 0; m < 2; m++)
#pragma unroll
        for (int n = 0; n < 8; n++)
#pragma unroll
            for (int q = 0; q < 4; q++) fr.c[m][n][q] = 0.f;

    uint32_t sbase = (uint32_t)__cvta_generic_to_shared(sm);
    uint32_t stA[2] = { sbase, sbase + STAGE_FLOATS * 4u };
    uint32_t stB[2] = { sbase + TA_FLOATS * 4u, sbase + (STAGE_FLOATS + TA_FLOATS) * 4u };
    FragAddr fa = make_addr();
    int ks0 = (threadIdx.x >> 5) & 3;
    int nchunks = D_ / KC;

    issue_chunk(A, D_, Bp, D_, 0, stA[0], stB[0]);
    for (int c = 0; c < nchunks; c++) {
        asm volatile("cp.async.wait_group 0;" ::: "memory");
        __syncthreads();
        uint32_t sA = stA[c & 1], sB = stB[c & 1];
        compute_ks(sA, sB, fa, ks0, fr);
        if (c + 1 < nchunks)
            issue_chunk(A, D_, Bp, D_, (c + 1) * KC, stA[(c + 1) & 1], stB[(c + 1) & 1]);
#pragma unroll
        for (int t = 1; t < 4; t++)
            compute_ks(sA, sB, fa, (ks0 + t) & 3, fr);
    }

    int tid = threadIdx.x, wid = tid >> 5, lane = tid & 31;
    int wr = (wid >> 1) * 32, wc = (wid & 1) * 64;
    int g = lane >> 2, tg = lane & 3;
    const float scl = 0.036084391824351615f;  // 1/sqrt(768)
    float* C = g_S + (size_t)b * T_ * T_;
#pragma unroll
    for (int m = 0; m < 2; m++) {
        int r0 = i0 + wr + m * 16 + g;
#pragma unroll
        for (int n = 0; n < 8; n++) {
            int cc = j0 + wc + n * 8 + tg * 2;
            float2 v0 = make_float2(fr.c[m][n][0] * scl, fr.c[m][n][1] * scl);
            float2 v1 = make_float2(fr.c[m][n][2] * scl, fr.c[m][n][3] * scl);
            *(float2*)(C + (size_t)r0 * T_ + cc) = v0;
            *(float2*)(C + (size_t)(r0 + 8) * T_ + cc) = v1;
        }
    }
}

// ---------------------------------------------------------------------------
// Kernel 2: per-row stats only: m = max_{j<=i} s, inv = 1/sum exp(s-m).
// Masked rows -> (0,0). No weight writes at all.
// ---------------------------------------------------------------------------
__global__ __launch_bounds__(256) void rowstat_kernel(const float* __restrict__ mask) {
    int row = blockIdx.x;
    int b = row >> 11;
    int i = row & (T_ - 1);
    int tid = threadIdx.x;

    if (mask[(size_t)b * T_ + i] == 0.0f) {
        if (tid == 0) g_stat[row] = make_float2(0.f, 0.f);
        return;
    }
    const float* srow = g_S + (size_t)b * T_ * T_ + (size_t)i * T_;

    __shared__ float sh[T_];
    __shared__ float red[8];

    int n = i + 1;
    float lm = -3.4e38f;
    for (int j = tid; j < n; j += 256) { float v = srow[j]; sh[j] = v; lm = fmaxf(lm, v); }
#pragma unroll
    for (int o = 16; o > 0; o >>= 1) lm = fmaxf(lm, __shfl_xor_sync(0xffffffffu, lm, o));
    if ((tid & 31) == 0) red[tid >> 5] = lm;
    __syncthreads();
    float m = red[0];
#pragma unroll
    for (int k = 1; k < 8; k++) m = fmaxf(m, red[k]);
    __syncthreads();

    float ls = 0.f;
    for (int j = tid; j < n; j += 256) ls += __expf(sh[j] - m);
#pragma unroll
    for (int o = 16; o > 0; o >>= 1) ls += __shfl_xor_sync(0xffffffffu, ls, o);
    if ((tid & 31) == 0) red[tid >> 5] = ls;
    __syncthreads();
    float l = red[0];
#pragma unroll
    for (int k = 1; k < 8; k++) l += red[k];

    if (tid == 0) g_stat[row] = make_float2(m, 1.0f / l);
}

// ---------------------------------------------------------------------------
// Kernel 2.5: Xt[b,d,j] = tf32(X[b,j,d]); Xc[b,j,d] = tf32(X[b,j,d]);
//             out[b,j,D+d] = X[b,j,d]  (concat half, unconverted)
// ---------------------------------------------------------------------------
__global__ __launch_bounds__(256) void transpose_concat_kernel(const float* __restrict__ X,
                                                               float* __restrict__ out) {
    __shared__ float t[32][33];
    int b = blockIdx.z, j0 = blockIdx.x * 32, d0 = blockIdx.y * 32;
    int tx = threadIdx.x, ty = threadIdx.y;
    const float* Xb = X + (size_t)b * T_ * D_;
    float* Xc = g_Xc + (size_t)b * T_ * D_;
#pragma unroll
    for (int r = 0; r < 32; r += 8) {
        float v = Xb[(size_t)(j0 + ty + r) * D_ + d0 + tx];
        float vt = __uint_as_float(f2tf32(v));
        t[ty + r][tx] = vt;
        out[((size_t)b * T_ + j0 + ty + r) * (2 * D_) + D_ + d0 + tx] = v;
        Xc[(size_t)(j0 + ty + r) * D_ + d0 + tx] = vt;
    }
    __syncthreads();
    float* Xt = g_Xt + (size_t)b * D_ * T_;
#pragma unroll
    for (int r = 0; r < 32; r += 8)
        Xt[(size_t)(d0 + ty + r) * T_ + j0 + tx] = t[tx][ty + r];
}

// ---------------------------------------------------------------------------
// Kernel 3 (fused): out[b,i,d] = sum_{j<=i} softmax-weight(i,j)*Xt[b,d,j].
// Raw S chunks arrive via cp.async; an in-smem transform applies
// w = (j<=i && mask_j) ? exp(s-m_i)*inv_i : 0 (tf32-rounded) before ldmatrix.
// K runs to exactly i0+64. i-tiles DESCENDING-K (wave LB).
// ---------------------------------------------------------------------------
__global__ void __launch_bounds__(128, 4) pv_fused_kernel(const float* __restrict__ mask,
                                                          float* __restrict__ out) {
    int b = blockIdx.z;
    int i0 = (gridDim.y - 1 - blockIdx.y) * 64;    // big K first
    int d0 = blockIdx.x * 128;

    extern __shared__ uint32_t sm[];
    const float* A = g_S + (size_t)b * T_ * T_ + (size_t)i0 * T_;
    const float* Bp = g_Xt + (size_t)b * D_ * T_ + (size_t)d0 * T_;
    const float* mrow = mask + (size_t)b * T_;

    int tid = threadIdx.x;
    int trow = tid >> 3, tf4 = tid & 7;            // transform/producer layout

    // Per-thread row stats (4 rows each, matching producer rows trow + p*16)
    float2 st[4];
#pragma unroll
    for (int p = 0; p < 4; p++)
        st[p] = g_stat[(size_t)b * T_ + i0 + trow + p * 16];

    Frag fr;
#pragma unroll
    for (int m = 0; m < 2; m++)
#pragma unroll
        for (int n = 0; n < 8; n++)
#pragma unroll
            for (int q = 0; q < 4; q++) fr.c[m][n][q] = 0.f;

    uint32_t sbase = (uint32_t)__cvta_generic_to_shared(sm);
    uint32_t stA[2] = { sbase, sbase + STAGE_FLOATS * 4u };
    uint32_t stB[2] = { sbase + TA_FLOATS * 4u, sbase + (STAGE_FLOATS + TA_FLOATS) * 4u };
    float* aGen[2] = { (float*)sm, (float*)sm + STAGE_FLOATS };  // generic ptrs to A stages
    FragAddr fa = make_addr();
    int ks0 = (tid >> 5) & 3;
    int nchunks = (i0 + 64) / KC;

    issue_chunk(A, T_, Bp, T_, 0, stA[0], stB[0]);
    for (int c = 0; c < nchunks; c++) {
        // mask values for this thread's 4 j-columns (same for all 4 rows)
        float4 mj = *(const float4*)(mrow + c * KC + tf4 * 4);
        asm volatile("cp.async.wait_group 0;" ::: "memory");
        __syncthreads();
        if (c + 1 < nchunks)
            issue_chunk(A, T_, Bp, T_, (c + 1) * KC, stA[(c + 1) & 1], stB[(c + 1) & 1]);

        // In-place transform of raw scores -> tf32 weights (stage c&1 A region)
        {
            float* aS = aGen[c & 1];
            int jb = c * KC + tf4 * 4;
#pragma unroll
            for (int p = 0; p < 4; p++) {
                float* ptr = aS + (trow + p * 16) * LDS_ + tf4 * 4;
                float4 s = *(float4*)ptr;
                int ig = i0 + trow + p * 16;
                float m = st[p].x, inv = st[p].y;
                float4 w;
                w.x = (jb + 0 <= ig && mj.x != 0.f) ? __expf(s.x - m) * inv : 0.f;
                w.y = (jb + 1 <= ig && mj.y != 0.f) ? __expf(s.y - m) * inv : 0.f;
                w.z = (jb + 2 <= ig && mj.z != 0.f) ? __expf(s.z - m) * inv : 0.f;
                w.w = (jb + 3 <= ig && mj.w != 0.f) ? __expf(s.w - m) * inv : 0.f;
                w.x = __uint_as_float(f2tf32(w.x));
                w.y = __uint_as_float(f2tf32(w.y));
                w.z = __uint_as_float(f2tf32(w.z));
                w.w = __uint_as_float(f2tf32(w.w));
                *(float4*)ptr = w;
            }
        }
        __syncthreads();   // transformed A visible to all warps

        uint32_t sA = stA[c & 1], sB = stB[c & 1];
#pragma unroll
        for (int t = 0; t < 4; t++)
            compute_ks(sA, sB, fa, (ks0 + t) & 3, fr);
    }

    int wid = tid >> 5, lane = tid & 31;
    int wr = (wid >> 1) * 32, wc = (wid & 1) * 64;
    int g = lane >> 2, tg = lane & 3;
#pragma unroll
    for (int m = 0; m < 2; m++) {
        int r0 = i0 + wr + m * 16 + g;
#pragma unroll
        for (int n = 0; n < 8; n++) {
            int cc = d0 + wc + n * 8 + tg * 2;
            float2 v0 = make_float2(fr.c[m][n][0], fr.c[m][n][1]);
            float2 v1 = make_float2(fr.c[m][n][2], fr.c[m][n][3]);
            *(float2*)(out + ((size_t)b * T_ + r0) * (2 * D_) + cc) = v0;
            *(float2*)(out + ((size_t)b * T_ + r0 + 8) * (2 * D_) + cc) = v1;
        }
    }
}

extern "C" void kernel_launch(void* const* d_in, const int* in_sizes, int n_in,
                              void* d_out, int out_size) {
    const float* X = (const float*)d_in[0];
    const float* mask = (const float*)d_in[1];
    // d_in[2] (proposition_matrix) is unused by the reference computation.
    float* out = (float*)d_out;

    cudaFuncSetAttribute(qk_mma_kernel, cudaFuncAttributeMaxDynamicSharedMemorySize, SMEM_DYN);
    cudaFuncSetAttribute(pv_fused_kernel, cudaFuncAttributeMaxDynamicSharedMemorySize, SMEM_DYN);

    dim3 gt(T_ / 32, D_ / 32, B_);
    transpose_concat_kernel<<<gt, dim3(32, 8)>>>(X, out);

    dim3 g1(T_ / 128, T_ / 64, B_);
    qk_mma_kernel<<<g1, 128, SMEM_DYN>>>();

    rowstat_kernel<<<B_ * T_, 256>>>(mask);

    dim3 g3(D_ / 128, T_ / 64, B_);
    pv_fused_kernel<<<g3, 128, SMEM_DYN>>>(mask, out);
}

// round 14
// speedup vs baseline: 1.1532x; 1.1532x over previous
#include <cuda_runtime.h>
#include <cuda.h>
#include <stdint.h>
#include <math.h>

#define B_ 8
#define T_ 2048
#define D_ 768
#define KC 32
#define LDS_ 36                         // padded row stride (floats)
#define TA_FLOATS (64 * LDS_)           // 2304 floats: A tile (64 rows)
#define TB_FLOATS (128 * LDS_)          // 4608 floats: B tile (128 rows)
#define STAGE_FLOATS (TA_FLOATS + TB_FLOATS)
#define SMEM_DYN (2 * STAGE_FLOATS * 4) // 2 stages = 55296 B
#define QK_TILES 272                    // lower-triangle (64x128) tiles per batch

// Scratch: scores->(in-place) weights; transposed tf32 X; converted row-major X.
__device__ float g_S[(size_t)B_ * T_ * T_];
__device__ float g_Xt[(size_t)B_ * D_ * T_];
__device__ float g_Xc[(size_t)B_ * T_ * D_];

__device__ __forceinline__ uint32_t f2tf32(float v) {
    uint32_t o;
    asm("cvt.rna.tf32.f32 %0, %1;" : "=r"(o) : "f"(v));
    return o;
}

__device__ __forceinline__ void mma_tf32(float& c0, float& c1, float& c2, float& c3,
                                         uint32_t a0, uint32_t a1, uint32_t a2, uint32_t a3,
                                         uint32_t b0, uint32_t b1) {
    asm volatile(
        "mma.sync.aligned.m16n8k8.row.col.f32.tf32.tf32.f32 "
        "{%0,%1,%2,%3}, {%4,%5,%6,%7}, {%8,%9}, {%0,%1,%2,%3};"
        : "+f"(c0), "+f"(c1), "+f"(c2), "+f"(c3)
        : "r"(a0), "r"(a1), "r"(a2), "r"(a3), "r"(b0), "r"(b1));
}

__device__ __forceinline__ void ldsm_x4(uint32_t& r0, uint32_t& r1, uint32_t& r2,
                                        uint32_t& r3, uint32_t addr) {
    asm volatile("ldmatrix.sync.aligned.m8n8.x4.shared.b16 {%0,%1,%2,%3}, [%4];"
                 : "=r"(r0), "=r"(r1), "=r"(r2), "=r"(r3) : "r"(addr));
}

struct Frag { float c[2][8][4]; };
struct FragAddr { uint32_t a0, a1, b0, b1, b2, b3; };

__device__ __forceinline__ FragAddr make_addr() {
    int tid = threadIdx.x, wid = tid >> 5, lane = tid & 31;
    int wr = (wid >> 1) * 32;
    int wc = (wid & 1) * 64;
    FragAddr fa;
    uint32_t arow = (uint32_t)(wr + (lane & 7) + ((lane >> 3) & 1) * 8);
    uint32_t akof = (uint32_t)((lane >> 4) & 1) * 4u;
    fa.a0 = (arow * LDS_ + akof) * 4u;
    fa.a1 = ((arow + 16) * LDS_ + akof) * 4u;
    uint32_t brow = (uint32_t)(wc + ((lane >> 4) & 1) * 8 + (lane & 7));
    uint32_t bkof = (uint32_t)((lane >> 3) & 1) * 4u;
    fa.b0 = ((brow + 0) * LDS_ + bkof) * 4u;
    fa.b1 = ((brow + 16) * LDS_ + bkof) * 4u;
    fa.b2 = ((brow + 32) * LDS_ + bkof) * 4u;
    fa.b3 = ((brow + 48) * LDS_ + bkof) * 4u;
    return fa;
}

__device__ __forceinline__ void compute_ks(uint32_t sA, uint32_t sB, const FragAddr& fa,
                                           int ksIdx, Frag& fr) {
    uint32_t kb = (uint32_t)ksIdx * 32u;
    uint32_t a[2][4];
    uint32_t bb[16];
    ldsm_x4(a[0][0], a[0][1], a[0][2], a[0][3], sA + fa.a0 + kb);
    ldsm_x4(a[1][0], a[1][1], a[1][2], a[1][3], sA + fa.a1 + kb);
    ldsm_x4(bb[0],  bb[1],  bb[2],  bb[3],  sB + fa.b0 + kb);
    ldsm_x4(bb[4],  bb[5],  bb[6],  bb[7],  sB + fa.b1 + kb);
    ldsm_x4(bb[8],  bb[9],  bb[10], bb[11], sB + fa.b2 + kb);
    ldsm_x4(bb[12], bb[13], bb[14], bb[15], sB + fa.b3 + kb);
#pragma unroll
    for (int n = 0; n < 8; n++) {
        uint32_t b0 = bb[(n >> 1) * 4 + (n & 1) * 2];
        uint32_t b1 = bb[(n >> 1) * 4 + (n & 1) * 2 + 1];
#pragma unroll
        for (int m = 0; m < 2; m++)
            mma_tf32(fr.c[m][n][0], fr.c[m][n][1], fr.c[m][n][2], fr.c[m][n][3],
                     a[m][0], a[m][1], a[m][2], a[m][3], b0, b1);
    }
}

// cp.async producer: A chunk (64x32) + B chunk (128x32) into given stage.
__device__ __forceinline__ void issue_chunk(const float* __restrict__ A, int lda,
                                            const float* __restrict__ Bp, int ldb,
                                            int k0, uint32_t sA, uint32_t sB) {
    int tid = threadIdx.x;
    int row = tid >> 3, f4 = tid & 7;
#pragma unroll
    for (int p = 0; p < 4; p++) {
        int r = row + p * 16;
        const float* ga = A + (size_t)r * lda + k0 + f4 * 4;
        uint32_t da = sA + (uint32_t)(r * LDS_ + f4 * 4) * 4u;
        asm volatile("cp.async.cg.shared.global [%0], [%1], 16;" :: "r"(da), "l"(ga));
    }
#pragma unroll
    for (int p = 0; p < 8; p++) {
        int r = row + p * 16;
        const float* gb = Bp + (size_t)r * ldb + k0 + f4 * 4;
        uint32_t db = sB + (uint32_t)(r * LDS_ + f4 * 4) * 4u;
        asm volatile("cp.async.cg.shared.global [%0], [%1], 16;" :: "r"(db), "l"(gb));
    }
    asm volatile("cp.async.commit_group;" ::: "memory");
}

// R12 mainloop: single barrier per chunk, warp-staggered ks, mid-chunk producer.
__device__ __forceinline__ void run_gemm(const float* __restrict__ A, int lda,
                                         const float* __restrict__ Bp, int ldb,
                                         int nchunks, uint32_t* sm, Frag& fr) {
#pragma unroll
    for (int m = 0; m < 2; m++)
#pragma unroll
        for (int n = 0; n < 8; n++)
#pragma unroll
            for (int q = 0; q < 4; q++) fr.c[m][n][q] = 0.f;

    uint32_t sbase = (uint32_t)__cvta_generic_to_shared(sm);
    uint32_t stA[2] = { sbase, sbase + STAGE_FLOATS * 4u };
    uint32_t stB[2] = { sbase + TA_FLOATS * 4u, sbase + (STAGE_FLOATS + TA_FLOATS) * 4u };

    FragAddr fa = make_addr();
    int ks0 = (threadIdx.x >> 5) & 3;

    issue_chunk(A, lda, Bp, ldb, 0, stA[0], stB[0]);
    for (int c = 0; c < nchunks; c++) {
        asm volatile("cp.async.wait_group 0;" ::: "memory");
        __syncthreads();
        uint32_t sA = stA[c & 1], sB = stB[c & 1];
        compute_ks(sA, sB, fa, ks0, fr);
        if (c + 1 < nchunks)
            issue_chunk(A, lda, Bp, ldb, (c + 1) * KC, stA[(c + 1) & 1], stB[(c + 1) & 1]);
#pragma unroll
        for (int t = 1; t < 4; t++)
            compute_ks(sA, sB, fa, (ks0 + t) & 3, fr);
    }
}

// ---------------------------------------------------------------------------
// Kernel 1: S[b,i,j] = Xc[b,i,:].Xc[b,j,:] / sqrt(D).
// Compacted grid: blockIdx.x enumerates the 272 active lower-triangle tiles.
// Pair p (tile-rows 2p,2p+1) holds 2(p+1) tiles starting at offset p(p+1).
// ---------------------------------------------------------------------------
__global__ void __launch_bounds__(128, 4) qk_mma_kernel() {
    int b = blockIdx.z;
    int t = blockIdx.x;
    int p = (int)((sqrtf(4.0f * (float)t + 1.0f) - 1.0f) * 0.5f);
    while ((p + 1) * (p + 2) <= t) p++;
    while (p * (p + 1) > t) p--;
    int r = t - p * (p + 1);
    int y = 2 * p + (r >= p + 1);
    int x = (r >= p + 1) ? r - (p + 1) : r;
    int i0 = y * 64;
    int j0 = x * 128;

    extern __shared__ uint32_t sm[];
    const float* A = g_Xc + (size_t)b * T_ * D_ + (size_t)i0 * D_;
    const float* Bp = g_Xc + (size_t)b * T_ * D_ + (size_t)j0 * D_;

    Frag fr;
    run_gemm(A, D_, Bp, D_, D_ / KC, sm, fr);

    int tid = threadIdx.x, wid = tid >> 5, lane = tid & 31;
    int wr = (wid >> 1) * 32, wc = (wid & 1) * 64;
    int g = lane >> 2, tg = lane & 3;
    const float scl = 0.036084391824351615f;  // 1/sqrt(768)
    float* C = g_S + (size_t)b * T_ * T_;
#pragma unroll
    for (int m = 0; m < 2; m++) {
        int r0 = i0 + wr + m * 16 + g;
#pragma unroll
        for (int n = 0; n < 8; n++) {
            int cc = j0 + wc + n * 8 + tg * 2;
            float2 v0 = make_float2(fr.c[m][n][0] * scl, fr.c[m][n][1] * scl);
            float2 v1 = make_float2(fr.c[m][n][2] * scl, fr.c[m][n][3] * scl);
            *(float2*)(C + (size_t)r0 * T_ + cc) = v0;
            *(float2*)(C + (size_t)(r0 + 8) * T_ + cc) = v1;
        }
    }
}

// ---------------------------------------------------------------------------
// Kernel 2: in-place causal softmax + post-softmax sit_mask zeroing.
// float4 passes; exp cached in smem (single MUFU pass). Writes only up to
// round_up(i+1,128) — pv never reads beyond it.
// ---------------------------------------------------------------------------
__global__ __launch_bounds__(256) void softmax_kernel(const float* __restrict__ mask) {
    int row = blockIdx.x;
    int b = row >> 11;
    int i = row & (T_ - 1);
    float* srow = g_S + (size_t)b * T_ * T_ + (size_t)i * T_;
    const float* mrow = mask + (size_t)b * T_;
    int tid = threadIdx.x;
    int nend = (i + 128) & ~127;     // round_up(i+1, 128): pv read bound

    __shared__ float sh[T_];
    __shared__ float red[8];

    if (mrow[i] == 0.0f) {
        float4 z = make_float4(0.f, 0.f, 0.f, 0.f);
        for (int j4 = tid; j4 < nend / 4; j4 += 256) ((float4*)srow)[j4] = z;
        return;
    }

    int n = i + 1;
    int n4 = n >> 2;                 // full float4s
    int ntail = n4 * 4;

    // Pass 1: load + max
    float lm = -3.4e38f;
    for (int j4 = tid; j4 < n4; j4 += 256) {
        float4 v = ((const float4*)srow)[j4];
        ((float4*)sh)[j4] = v;
        lm = fmaxf(fmaxf(fmaxf(lm, v.x), fmaxf(v.y, v.z)), v.w);
    }
    for (int j = ntail + tid; j < n; j += 256) { float v = srow[j]; sh[j] = v; lm = fmaxf(lm, v); }
#pragma unroll
    for (int o = 16; o > 0; o >>= 1) lm = fmaxf(lm, __shfl_xor_sync(0xffffffffu, lm, o));
    if ((tid & 31) == 0) red[tid >> 5] = lm;
    __syncthreads();
    float m = red[0];
#pragma unroll
    for (int k = 1; k < 8; k++) m = fmaxf(m, red[k]);
    __syncthreads();

    // Pass 2: exp (cached back to smem) + sum
    float ls = 0.f;
    for (int j4 = tid; j4 < n4; j4 += 256) {
        float4 v = ((float4*)sh)[j4];
        v.x = __expf(v.x - m); v.y = __expf(v.y - m);
        v.z = __expf(v.z - m); v.w = __expf(v.w - m);
        ((float4*)sh)[j4] = v;
        ls += (v.x + v.y) + (v.z + v.w);
    }
    for (int j = ntail + tid; j < n; j += 256) { float e = __expf(sh[j] - m); sh[j] = e; ls += e; }
#pragma unroll
    for (int o = 16; o > 0; o >>= 1) ls += __shfl_xor_sync(0xffffffffu, ls, o);
    if ((tid & 31) == 0) red[tid >> 5] = ls;
    __syncthreads();
    float l = red[0];
#pragma unroll
    for (int k = 1; k < 8; k++) l += red[k];
    float inv = 1.0f / l;
    __syncthreads();

    // Pass 3: masked tf32 weights from cached exps
    for (int j4 = tid; j4 < nend / 4; j4 += 256) {
        int jb = j4 * 4;
        float4 mj = ((const float4*)mrow)[j4];
        float4 w;
        w.x = (jb + 0 < n && mj.x != 0.f) ? sh[jb + 0] * inv : 0.f;
        w.y = (jb + 1 < n && mj.y != 0.f) ? sh[jb + 1] * inv : 0.f;
        w.z = (jb + 2 < n && mj.z != 0.f) ? sh[jb + 2] * inv : 0.f;
        w.w = (jb + 3 < n && mj.w != 0.f) ? sh[jb + 3] * inv : 0.f;
        w.x = __uint_as_float(f2tf32(w.x));
        w.y = __uint_as_float(f2tf32(w.y));
        w.z = __uint_as_float(f2tf32(w.z));
        w.w = __uint_as_float(f2tf32(w.w));
        ((float4*)srow)[j4] = w;
    }
}

// ---------------------------------------------------------------------------
// Kernel 2.5: Xt[b,d,j] = tf32(X[b,j,d]); Xc[b,j,d] = tf32(X[b,j,d]);
//             out[b,j,D+d] = X[b,j,d]  (concat half, unconverted)
// ---------------------------------------------------------------------------
__global__ __launch_bounds__(256) void transpose_concat_kernel(const float* __restrict__ X,
                                                               float* __restrict__ out) {
    __shared__ float t[32][33];
    int b = blockIdx.z, j0 = blockIdx.x * 32, d0 = blockIdx.y * 32;
    int tx = threadIdx.x, ty = threadIdx.y;
    const float* Xb = X + (size_t)b * T_ * D_;
    float* Xc = g_Xc + (size_t)b * T_ * D_;
#pragma unroll
    for (int r = 0; r < 32; r += 8) {
        float v = Xb[(size_t)(j0 + ty + r) * D_ + d0 + tx];
        float vt = __uint_as_float(f2tf32(v));
        t[ty + r][tx] = vt;
        out[((size_t)b * T_ + j0 + ty + r) * (2 * D_) + D_ + d0 + tx] = v;
        Xc[(size_t)(j0 + ty + r) * D_ + d0 + tx] = vt;
    }
    __syncthreads();
    float* Xt = g_Xt + (size_t)b * D_ * T_;
#pragma unroll
    for (int r = 0; r < 32; r += 8)
        Xt[(size_t)(d0 + ty + r) * T_ + j0 + tx] = t[tx][ty + r];
}

// ---------------------------------------------------------------------------
// Kernel 3: out[b,i,d] = sum_j W[b,i,j]*Xt[b,d,j]  (K truncated at i0+64,
// rounded up to 128). i-tiles mapped DESCENDING-K (wave LB).
// ---------------------------------------------------------------------------
__global__ void __launch_bounds__(128, 4) pv_mma_kernel(float* __restrict__ out) {
    int b = blockIdx.z;
    int i0 = (gridDim.y - 1 - blockIdx.y) * 64;    // big K first
    int d0 = blockIdx.x * 128;

    extern __shared__ uint32_t sm[];
    const float* A = g_S + (size_t)b * T_ * T_ + (size_t)i0 * T_;
    const float* Bp = g_Xt + (size_t)b * D_ * T_ + (size_t)d0 * T_;

    int kend = (i0 + 128) & ~127;   // W rows valid to 128-boundary (softmax zero-fills)
    Frag fr;
    run_gemm(A, T_, Bp, T_, kend / KC, sm, fr);

    int tid = threadIdx.x, wid = tid >> 5, lane = tid & 31;
    int wr = (wid >> 1) * 32, wc = (wid & 1) * 64;
    int g = lane >> 2, tg = lane & 3;
#pragma unroll
    for (int m = 0; m < 2; m++) {
        int r0 = i0 + wr + m * 16 + g;
#pragma unroll
        for (int n = 0; n < 8; n++) {
            int cc = d0 + wc + n * 8 + tg * 2;
            float2 v0 = make_float2(fr.c[m][n][0], fr.c[m][n][1]);
            float2 v1 = make_float2(fr.c[m][n][2], fr.c[m][n][3]);
            *(float2*)(out + ((size_t)b * T_ + r0) * (2 * D_) + cc) = v0;
            *(float2*)(out + ((size_t)b * T_ + r0 + 8) * (2 * D_) + cc) = v1;
        }
    }
}

extern "C" void kernel_launch(void* const* d_in, const int* in_sizes, int n_in,
                              void* d_out, int out_size) {
    const float* X = (const float*)d_in[0];
    const float* mask = (const float*)d_in[1];
    // d_in[2] (proposition_matrix) is unused by the reference computation.
    float* out = (float*)d_out;

    cudaFuncSetAttribute(qk_mma_kernel, cudaFuncAttributeMaxDynamicSharedMemorySize, SMEM_DYN);
    cudaFuncSetAttribute(pv_mma_kernel, cudaFuncAttributeMaxDynamicSharedMemorySize, SMEM_DYN);

    dim3 gt(T_ / 32, D_ / 32, B_);
    transpose_concat_kernel<<<gt, dim3(32, 8)>>>(X, out);

    dim3 g1(QK_TILES, 1, B_);
    qk_mma_kernel<<<g1, 128, SMEM_DYN>>>();

    softmax_kernel<<<B_ * T_, 256>>>(mask);

    dim3 g3(D_ / 128, T_ / 64, B_);
    pv_mma_kernel<<<g3, 128, SMEM_DYN>>>(out);
}

// round 15
// speedup vs baseline: 1.5593x; 1.3522x over previous
#include <cuda_runtime.h>
#include <cuda.h>
#include <stdint.h>
#include <math.h>

#define B_ 8
#define T_ 2048
#define D_ 768
#define KC 32
#define LDS_ 36                         // padded row stride (floats)
#define TA_FLOATS (64 * LDS_)           // 2304 floats: A tile (64 rows)
#define TB_FLOATS (128 * LDS_)          // 4608 floats: B tile (128 rows)
#define STAGE_FLOATS (TA_FLOATS + TB_FLOATS)
#define SMEM_DYN (2 * STAGE_FLOATS * 4) // 2 stages = 55296 B

// Scratch: compact scores->(in-place) weights; transposed tf32 X; converted X;
// compact->orig row map + counts.
__device__ float g_S[(size_t)B_ * T_ * T_];
__device__ float g_Xt[(size_t)B_ * D_ * T_];
__device__ float g_Xc[(size_t)B_ * T_ * D_];
__device__ int g_idx[B_][T_];
__device__ int g_nc[B_];

__device__ __forceinline__ uint32_t f2tf32(float v) {
    uint32_t o;
    asm("cvt.rna.tf32.f32 %0, %1;" : "=r"(o) : "f"(v));
    return o;
}

__device__ __forceinline__ void mma_tf32(float& c0, float& c1, float& c2, float& c3,
                                         uint32_t a0, uint32_t a1, uint32_t a2, uint32_t a3,
                                         uint32_t b0, uint32_t b1) {
    asm volatile(
        "mma.sync.aligned.m16n8k8.row.col.f32.tf32.tf32.f32 "
        "{%0,%1,%2,%3}, {%4,%5,%6,%7}, {%8,%9}, {%0,%1,%2,%3};"
        : "+f"(c0), "+f"(c1), "+f"(c2), "+f"(c3)
        : "r"(a0), "r"(a1), "r"(a2), "r"(a3), "r"(b0), "r"(b1));
}

__device__ __forceinline__ void ldsm_x4(uint32_t& r0, uint32_t& r1, uint32_t& r2,
                                        uint32_t& r3, uint32_t addr) {
    asm volatile("ldmatrix.sync.aligned.m8n8.x4.shared.b16 {%0,%1,%2,%3}, [%4];"
                 : "=r"(r0), "=r"(r1), "=r"(r2), "=r"(r3) : "r"(addr));
}

struct Frag { float c[2][8][4]; };
struct FragAddr { uint32_t a0, a1, b0, b1, b2, b3; };

__device__ __forceinline__ FragAddr make_addr() {
    int tid = threadIdx.x, wid = tid >> 5, lane = tid & 31;
    int wr = (wid >> 1) * 32;
    int wc = (wid & 1) * 64;
    FragAddr fa;
    uint32_t arow = (uint32_t)(wr + (lane & 7) + ((lane >> 3) & 1) * 8);
    uint32_t akof = (uint32_t)((lane >> 4) & 1) * 4u;
    fa.a0 = (arow * LDS_ + akof) * 4u;
    fa.a1 = ((arow + 16) * LDS_ + akof) * 4u;
    uint32_t brow = (uint32_t)(wc + ((lane >> 4) & 1) * 8 + (lane & 7));
    uint32_t bkof = (uint32_t)((lane >> 3) & 1) * 4u;
    fa.b0 = ((brow + 0) * LDS_ + bkof) * 4u;
    fa.b1 = ((brow + 16) * LDS_ + bkof) * 4u;
    fa.b2 = ((brow + 32) * LDS_ + bkof) * 4u;
    fa.b3 = ((brow + 48) * LDS_ + bkof) * 4u;
    return fa;
}

__device__ __forceinline__ void compute_ks(uint32_t sA, uint32_t sB, const FragAddr& fa,
                                           int ksIdx, Frag& fr) {
    uint32_t kb = (uint32_t)ksIdx * 32u;
    uint32_t a[2][4];
    uint32_t bb[16];
    ldsm_x4(a[0][0], a[0][1], a[0][2], a[0][3], sA + fa.a0 + kb);
    ldsm_x4(a[1][0], a[1][1], a[1][2], a[1][3], sA + fa.a1 + kb);
    ldsm_x4(bb[0],  bb[1],  bb[2],  bb[3],  sB + fa.b0 + kb);
    ldsm_x4(bb[4],  bb[5],  bb[6],  bb[7],  sB + fa.b1 + kb);
    ldsm_x4(bb[8],  bb[9],  bb[10], bb[11], sB + fa.b2 + kb);
    ldsm_x4(bb[12], bb[13], bb[14], bb[15], sB + fa.b3 + kb);
#pragma unroll
    for (int n = 0; n < 8; n++) {
        uint32_t b0 = bb[(n >> 1) * 4 + (n & 1) * 2];
        uint32_t b1 = bb[(n >> 1) * 4 + (n & 1) * 2 + 1];
#pragma unroll
        for (int m = 0; m < 2; m++)
            mma_tf32(fr.c[m][n][0], fr.c[m][n][1], fr.c[m][n][2], fr.c[m][n][3],
                     a[m][0], a[m][1], a[m][2], a[m][3], b0, b1);
    }
}

// cp.async producer: A rows via precomputed per-thread row pointers (supports
// gather); B rows regular strided.
__device__ __forceinline__ void issue_chunk(const float* const* aPtr,
                                            const float* __restrict__ Bp, int ldb,
                                            int k0, uint32_t sA, uint32_t sB) {
    int tid = threadIdx.x;
    int row = tid >> 3, f4 = tid & 7;
#pragma unroll
    for (int p = 0; p < 4; p++) {
        const float* ga = aPtr[p] + k0 + f4 * 4;
        uint32_t da = sA + (uint32_t)((row + p * 16) * LDS_ + f4 * 4) * 4u;
        asm volatile("cp.async.cg.shared.global [%0], [%1], 16;" :: "r"(da), "l"(ga));
    }
#pragma unroll
    for (int p = 0; p < 8; p++) {
        int r = row + p * 16;
        const float* gb = Bp + (size_t)r * ldb + k0 + f4 * 4;
        uint32_t db = sB + (uint32_t)(r * LDS_ + f4 * 4) * 4u;
        asm volatile("cp.async.cg.shared.global [%0], [%1], 16;" :: "r"(db), "l"(gb));
    }
    asm volatile("cp.async.commit_group;" ::: "memory");
}

// R12/R14 mainloop: single barrier per chunk, warp-staggered ks, mid-chunk producer.
__device__ __forceinline__ void run_gemm(const float* const* aPtr,
                                         const float* __restrict__ Bp, int ldb,
                                         int nchunks, uint32_t* sm, Frag& fr) {
#pragma unroll
    for (int m = 0; m < 2; m++)
#pragma unroll
        for (int n = 0; n < 8; n++)
#pragma unroll
            for (int q = 0; q < 4; q++) fr.c[m][n][q] = 0.f;

    uint32_t sbase = (uint32_t)__cvta_generic_to_shared(sm);
    uint32_t stA[2] = { sbase, sbase + STAGE_FLOATS * 4u };
    uint32_t stB[2] = { sbase + TA_FLOATS * 4u, sbase + (STAGE_FLOATS + TA_FLOATS) * 4u };

    FragAddr fa = make_addr();
    int ks0 = (threadIdx.x >> 5) & 3;

    issue_chunk(aPtr, Bp, ldb, 0, stA[0], stB[0]);
    for (int c = 0; c < nchunks; c++) {
        asm volatile("cp.async.wait_group 0;" ::: "memory");
        __syncthreads();
        uint32_t sA = stA[c & 1], sB = stB[c & 1];
        compute_ks(sA, sB, fa, ks0, fr);
        if (c + 1 < nchunks)
            issue_chunk(aPtr, Bp, ldb, (c + 1) * KC, stA[(c + 1) & 1], stB[(c + 1) & 1]);
#pragma unroll
        for (int t = 1; t < 4; t++)
            compute_ks(sA, sB, fa, (ks0 + t) & 3, fr);
    }
}

// ---------------------------------------------------------------------------
// Kernel 0: per-batch prefix scan of sit_mask -> compact row map g_idx, g_nc.
// Tail of g_idx filled with 0 (valid row; results discarded) for determinism.
// ---------------------------------------------------------------------------
__global__ __launch_bounds__(256) void mask_scan_kernel(const float* __restrict__ mask) {
    int b = blockIdx.x, tid = threadIdx.x;
    const float* mr = mask + (size_t)b * T_;
    __shared__ int wsums[8];
    int base = tid * 8;
    int loc[8]; int cnt = 0;
#pragma unroll
    for (int k = 0; k < 8; k++) { loc[k] = cnt; cnt += (mr[base + k] != 0.f) ? 1 : 0; }
    int lane = tid & 31, wid = tid >> 5;
    int v = cnt;
#pragma unroll
    for (int o = 1; o < 32; o <<= 1) {
        int u = __shfl_up_sync(0xffffffffu, v, o);
        if (lane >= o) v += u;
    }
    if (lane == 31) wsums[wid] = v;
    __syncthreads();
    int woff = 0;
    for (int w = 0; w < wid; w++) woff += wsums[w];
    int excl = woff + v - cnt;
#pragma unroll
    for (int k = 0; k < 8; k++)
        if (mr[base + k] != 0.f) g_idx[b][excl + loc[k]] = base + k;
    __syncthreads();
    int total = 0;
#pragma unroll
    for (int w = 0; w < 8; w++) total += wsums[w];
    if (tid == 0) g_nc[b] = total;
    for (int ci = total + tid; ci < T_; ci += 256) g_idx[b][ci] = 0;
}

// ---------------------------------------------------------------------------
// Kernel 1: S[b,ci,j] = Xc[idx[ci],:].Xc[j,:] / sqrt(D), compact rows.
// Early-outs: ci0 >= nc; j0 > max orig index in tile (causal triangle).
// ---------------------------------------------------------------------------
__global__ void __launch_bounds__(128, 4) qk_mma_kernel() {
    int b = blockIdx.z;
    int nc = g_nc[b];
    int ci0 = blockIdx.y * 64;
    int j0 = blockIdx.x * 128;
    if (ci0 >= nc) return;
    int maxi = g_idx[b][min(ci0 + 63, nc - 1)];
    if (j0 > maxi) return;

    extern __shared__ uint32_t sm[];
    const float* Xb = g_Xc + (size_t)b * T_ * D_;
    int trow = threadIdx.x >> 3;
    const float* aPtr[4];
#pragma unroll
    for (int p = 0; p < 4; p++)
        aPtr[p] = Xb + (size_t)g_idx[b][ci0 + trow + p * 16] * D_;
    const float* Bp = Xb + (size_t)j0 * D_;

    Frag fr;
    run_gemm(aPtr, Bp, D_, D_ / KC, sm, fr);

    int tid = threadIdx.x, wid = tid >> 5, lane = tid & 31;
    int wr = (wid >> 1) * 32, wc = (wid & 1) * 64;
    int g = lane >> 2, tg = lane & 3;
    const float scl = 0.036084391824351615f;  // 1/sqrt(768)
    float* C = g_S + (size_t)b * T_ * T_;
#pragma unroll
    for (int m = 0; m < 2; m++) {
        int r0 = ci0 + wr + m * 16 + g;
#pragma unroll
        for (int n = 0; n < 8; n++) {
            int cc = j0 + wc + n * 8 + tg * 2;
            float2 v0 = make_float2(fr.c[m][n][0] * scl, fr.c[m][n][1] * scl);
            float2 v1 = make_float2(fr.c[m][n][2] * scl, fr.c[m][n][3] * scl);
            *(float2*)(C + (size_t)r0 * T_ + cc) = v0;
            *(float2*)(C + (size_t)(r0 + 8) * T_ + cc) = v1;
        }
    }
}

// ---------------------------------------------------------------------------
// Kernel 2: softmax on compact rows (all unmasked). Zero-fills to the TILE's
// K bound round_up(idx[tile_last]+1,128) so pv's truncation is safe.
// ---------------------------------------------------------------------------
__global__ __launch_bounds__(256) void softmax_kernel(const float* __restrict__ mask) {
    int b = blockIdx.x >> 11;
    int ci = blockIdx.x & (T_ - 1);
    int nc = g_nc[b];
    if (ci >= nc) return;
    int i = g_idx[b][ci];
    int nend = (g_idx[b][min((ci & ~63) + 63, nc - 1)] + 128) & ~127;
    float* srow = g_S + (size_t)b * T_ * T_ + (size_t)ci * T_;
    const float* mrow = mask + (size_t)b * T_;
    int tid = threadIdx.x;

    __shared__ float sh[T_];
    __shared__ float red[8];

    int n = i + 1;
    int n4 = n >> 2;
    int ntail = n4 * 4;

    float lm = -3.4e38f;
    for (int j4 = tid; j4 < n4; j4 += 256) {
        float4 v = ((const float4*)srow)[j4];
        ((float4*)sh)[j4] = v;
        lm = fmaxf(fmaxf(fmaxf(lm, v.x), fmaxf(v.y, v.z)), v.w);
    }
    for (int j = ntail + tid; j < n; j += 256) { float v = srow[j]; sh[j] = v; lm = fmaxf(lm, v); }
#pragma unroll
    for (int o = 16; o > 0; o >>= 1) lm = fmaxf(lm, __shfl_xor_sync(0xffffffffu, lm, o));
    if ((tid & 31) == 0) red[tid >> 5] = lm;
    __syncthreads();
    float m = red[0];
#pragma unroll
    for (int k = 1; k < 8; k++) m = fmaxf(m, red[k]);
    __syncthreads();

    float ls = 0.f;
    for (int j4 = tid; j4 < n4; j4 += 256) {
        float4 v = ((float4*)sh)[j4];
        v.x = __expf(v.x - m); v.y = __expf(v.y - m);
        v.z = __expf(v.z - m); v.w = __expf(v.w - m);
        ((float4*)sh)[j4] = v;
        ls += (v.x + v.y) + (v.z + v.w);
    }
    for (int j = ntail + tid; j < n; j += 256) { float e = __expf(sh[j] - m); sh[j] = e; ls += e; }
#pragma unroll
    for (int o = 16; o > 0; o >>= 1) ls += __shfl_xor_sync(0xffffffffu, ls, o);
    if ((tid & 31) == 0) red[tid >> 5] = ls;
    __syncthreads();
    float l = red[0];
#pragma unroll
    for (int k = 1; k < 8; k++) l += red[k];
    float inv = 1.0f / l;
    __syncthreads();

    for (int j4 = tid; j4 < nend / 4; j4 += 256) {
        int jb = j4 * 4;
        float4 mj = ((const float4*)mrow)[j4];
        float4 w;
        w.x = (jb + 0 < n && mj.x != 0.f) ? sh[jb + 0] * inv : 0.f;
        w.y = (jb + 1 < n && mj.y != 0.f) ? sh[jb + 1] * inv : 0.f;
        w.z = (jb + 2 < n && mj.z != 0.f) ? sh[jb + 2] * inv : 0.f;
        w.w = (jb + 3 < n && mj.w != 0.f) ? sh[jb + 3] * inv : 0.f;
        w.x = __uint_as_float(f2tf32(w.x));
        w.y = __uint_as_float(f2tf32(w.y));
        w.z = __uint_as_float(f2tf32(w.z));
        w.w = __uint_as_float(f2tf32(w.w));
        ((float4*)srow)[j4] = w;
    }
}

// ---------------------------------------------------------------------------
// Kernel 2.5: Xt = tf32(X)^T; Xc = tf32(X); out concat half = X;
// masked rows: out[b,i,0:D] = 0 (their attention output is exactly zero).
// ---------------------------------------------------------------------------
__global__ __launch_bounds__(256) void transpose_concat_kernel(const float* __restrict__ X,
                                                               const float* __restrict__ mask,
                                                               float* __restrict__ out) {
    __shared__ float t[32][33];
    int b = blockIdx.z, j0 = blockIdx.x * 32, d0 = blockIdx.y * 32;
    int tx = threadIdx.x, ty = threadIdx.y;
    const float* Xb = X + (size_t)b * T_ * D_;
    float* Xc = g_Xc + (size_t)b * T_ * D_;
#pragma unroll
    for (int r = 0; r < 32; r += 8) {
        int j = j0 + ty + r;
        float v = Xb[(size_t)j * D_ + d0 + tx];
        float vt = __uint_as_float(f2tf32(v));
        t[ty + r][tx] = vt;
        float* orow = out + ((size_t)b * T_ + j) * (2 * D_);
        orow[D_ + d0 + tx] = v;
        if (mask[(size_t)b * T_ + j] == 0.f) orow[d0 + tx] = 0.f;
        Xc[(size_t)j * D_ + d0 + tx] = vt;
    }
    __syncthreads();
    float* Xt = g_Xt + (size_t)b * D_ * T_;
#pragma unroll
    for (int r = 0; r < 32; r += 8)
        Xt[(size_t)(d0 + ty + r) * T_ + j0 + tx] = t[tx][ty + r];
}

// ---------------------------------------------------------------------------
// Kernel 3: out[b,idx[ci],d] = sum_j W[ci,j]*Xt[d,j], compact rows, K to the
// tile bound. Epilogue scatters via idx with ci<nc guard. DESCENDING-K map.
// ---------------------------------------------------------------------------
__global__ void __launch_bounds__(128, 4) pv_mma_kernel(float* __restrict__ out) {
    int b = blockIdx.z;
    int nc = g_nc[b];
    int ci0 = (gridDim.y - 1 - blockIdx.y) * 64;
    int d0 = blockIdx.x * 128;
    if (ci0 >= nc) return;
    int kend = (g_idx[b][min(ci0 + 63, nc - 1)] + 128) & ~127;

    extern __shared__ uint32_t sm[];
    const float* Sb = g_S + (size_t)b * T_ * T_;
    int trow = threadIdx.x >> 3;
    const float* aPtr[4];
#pragma unroll
    for (int p = 0; p < 4; p++)
        aPtr[p] = Sb + (size_t)(ci0 + trow + p * 16) * T_;
    const float* Bp = g_Xt + (size_t)b * D_ * T_ + (size_t)d0 * T_;

    Frag fr;
    run_gemm(aPtr, Bp, T_, kend / KC, sm, fr);

    int tid = threadIdx.x, wid = tid >> 5, lane = tid & 31;
    int wr = (wid >> 1) * 32, wc = (wid & 1) * 64;
    int g = lane >> 2, tg = lane & 3;
#pragma unroll
    for (int m = 0; m < 2; m++) {
        int rc = ci0 + wr + m * 16 + g;
        int io0 = (rc < nc) ? g_idx[b][rc] : -1;
        int io1 = (rc + 8 < nc) ? g_idx[b][rc + 8] : -1;
        float* o0 = out + ((size_t)b * T_ + io0) * (2 * D_) + d0;
        float* o1 = out + ((size_t)b * T_ + io1) * (2 * D_) + d0;
#pragma unroll
        for (int n = 0; n < 8; n++) {
            int cc = wc + n * 8 + tg * 2;
            if (io0 >= 0) *(float2*)(o0 + cc) = make_float2(fr.c[m][n][0], fr.c[m][n][1]);
            if (io1 >= 0) *(float2*)(o1 + cc) = make_float2(fr.c[m][n][2], fr.c[m][n][3]);
        }
    }
}

extern "C" void kernel_launch(void* const* d_in, const int* in_sizes, int n_in,
                              void* d_out, int out_size) {
    const float* X = (const float*)d_in[0];
    const float* mask = (const float*)d_in[1];
    // d_in[2] (proposition_matrix) is unused by the reference computation.
    float* out = (float*)d_out;

    cudaFuncSetAttribute(qk_mma_kernel, cudaFuncAttributeMaxDynamicSharedMemorySize, SMEM_DYN);
    cudaFuncSetAttribute(pv_mma_kernel, cudaFuncAttributeMaxDynamicSharedMemorySize, SMEM_DYN);

    mask_scan_kernel<<<B_, 256>>>(mask);

    dim3 gt(T_ / 32, D_ / 32, B_);
    transpose_concat_kernel<<<gt, dim3(32, 8)>>>(X, mask, out);

    dim3 g1(T_ / 128, T_ / 64, B_);
    qk_mma_kernel<<<g1, 128, SMEM_DYN>>>();

    softmax_kernel<<<B_ * T_, 256>>>(mask);

    dim3 g3(D_ / 128, T_ / 64, B_);
    pv_mma_kernel<<<g3, 128, SMEM_DYN>>>(out);
}

// round 16
// speedup vs baseline: 1.9103x; 1.2251x over previous
#include <cuda_runtime.h>
#include <cuda.h>
#include <stdint.h>
#include <math.h>

#define B_ 8
#define T_ 2048
#define D_ 768
#define KC 32
#define LDS_ 36                         // padded row stride (floats)
#define TA_FLOATS (64 * LDS_)           // 2304 floats: A tile (64 rows)
#define TB_FLOATS (128 * LDS_)          // 4608 floats: B tile (128 rows)
#define STAGE_FLOATS (TA_FLOATS + TB_FLOATS)
#define SMEM_DYN (2 * STAGE_FLOATS * 4) // 2 stages = 55296 B

// Scratch: compact scores->(in-place, compact-j) weights; column-compacted
// transposed tf32 X; converted row-major X; compact maps.
__device__ float g_S[(size_t)B_ * T_ * T_];
__device__ float g_Xtc[(size_t)B_ * D_ * T_];   // [d][cj] = tf32(X[idx[cj]][d])
__device__ float g_Xc[(size_t)B_ * T_ * D_];
__device__ int g_idx[B_][T_];                   // compact -> orig
__device__ int g_rank[B_][T_];                  // orig -> compact (exclusive scan)
__device__ int g_nc[B_];

__device__ __forceinline__ uint32_t f2tf32(float v) {
    uint32_t o;
    asm("cvt.rna.tf32.f32 %0, %1;" : "=r"(o) : "f"(v));
    return o;
}

__device__ __forceinline__ void mma_tf32(float& c0, float& c1, float& c2, float& c3,
                                         uint32_t a0, uint32_t a1, uint32_t a2, uint32_t a3,
                                         uint32_t b0, uint32_t b1) {
    asm volatile(
        "mma.sync.aligned.m16n8k8.row.col.f32.tf32.tf32.f32 "
        "{%0,%1,%2,%3}, {%4,%5,%6,%7}, {%8,%9}, {%0,%1,%2,%3};"
        : "+f"(c0), "+f"(c1), "+f"(c2), "+f"(c3)
        : "r"(a0), "r"(a1), "r"(a2), "r"(a3), "r"(b0), "r"(b1));
}

__device__ __forceinline__ void ldsm_x4(uint32_t& r0, uint32_t& r1, uint32_t& r2,
                                        uint32_t& r3, uint32_t addr) {
    asm volatile("ldmatrix.sync.aligned.m8n8.x4.shared.b16 {%0,%1,%2,%3}, [%4];"
                 : "=r"(r0), "=r"(r1), "=r"(r2), "=r"(r3) : "r"(addr));
}

struct Frag { float c[2][8][4]; };
struct FragAddr { uint32_t a0, a1, b0, b1, b2, b3; };

__device__ __forceinline__ FragAddr make_addr() {
    int tid = threadIdx.x, wid = tid >> 5, lane = tid & 31;
    int wr = (wid >> 1) * 32;
    int wc = (wid & 1) * 64;
    FragAddr fa;
    uint32_t arow = (uint32_t)(wr + (lane & 7) + ((lane >> 3) & 1) * 8);
    uint32_t akof = (uint32_t)((lane >> 4) & 1) * 4u;
    fa.a0 = (arow * LDS_ + akof) * 4u;
    fa.a1 = ((arow + 16) * LDS_ + akof) * 4u;
    uint32_t brow = (uint32_t)(wc + ((lane >> 4) & 1) * 8 + (lane & 7));
    uint32_t bkof = (uint32_t)((lane >> 3) & 1) * 4u;
    fa.b0 = ((brow + 0) * LDS_ + bkof) * 4u;
    fa.b1 = ((brow + 16) * LDS_ + bkof) * 4u;
    fa.b2 = ((brow + 32) * LDS_ + bkof) * 4u;
    fa.b3 = ((brow + 48) * LDS_ + bkof) * 4u;
    return fa;
}

__device__ __forceinline__ void compute_ks(uint32_t sA, uint32_t sB, const FragAddr& fa,
                                           int ksIdx, Frag& fr) {
    uint32_t kb = (uint32_t)ksIdx * 32u;
    uint32_t a[2][4];
    uint32_t bb[16];
    ldsm_x4(a[0][0], a[0][1], a[0][2], a[0][3], sA + fa.a0 + kb);
    ldsm_x4(a[1][0], a[1][1], a[1][2], a[1][3], sA + fa.a1 + kb);
    ldsm_x4(bb[0],  bb[1],  bb[2],  bb[3],  sB + fa.b0 + kb);
    ldsm_x4(bb[4],  bb[5],  bb[6],  bb[7],  sB + fa.b1 + kb);
    ldsm_x4(bb[8],  bb[9],  bb[10], bb[11], sB + fa.b2 + kb);
    ldsm_x4(bb[12], bb[13], bb[14], bb[15], sB + fa.b3 + kb);
#pragma unroll
    for (int n = 0; n < 8; n++) {
        uint32_t b0 = bb[(n >> 1) * 4 + (n & 1) * 2];
        uint32_t b1 = bb[(n >> 1) * 4 + (n & 1) * 2 + 1];
#pragma unroll
        for (int m = 0; m < 2; m++)
            mma_tf32(fr.c[m][n][0], fr.c[m][n][1], fr.c[m][n][2], fr.c[m][n][3],
                     a[m][0], a[m][1], a[m][2], a[m][3], b0, b1);
    }
}

// cp.async producer: A rows via per-thread row pointers (supports gather);
// B rows regular strided.
__device__ __forceinline__ void issue_chunk(const float* const* aPtr,
                                            const float* __restrict__ Bp, int ldb,
                                            int k0, uint32_t sA, uint32_t sB) {
    int tid = threadIdx.x;
    int row = tid >> 3, f4 = tid & 7;
#pragma unroll
    for (int p = 0; p < 4; p++) {
        const float* ga = aPtr[p] + k0 + f4 * 4;
        uint32_t da = sA + (uint32_t)((row + p * 16) * LDS_ + f4 * 4) * 4u;
        asm volatile("cp.async.cg.shared.global [%0], [%1], 16;" :: "r"(da), "l"(ga));
    }
#pragma unroll
    for (int p = 0; p < 8; p++) {
        int r = row + p * 16;
        const float* gb = Bp + (size_t)r * ldb + k0 + f4 * 4;
        uint32_t db = sB + (uint32_t)(r * LDS_ + f4 * 4) * 4u;
        asm volatile("cp.async.cg.shared.global [%0], [%1], 16;" :: "r"(db), "l"(gb));
    }
    asm volatile("cp.async.commit_group;" ::: "memory");
}

// Mainloop: single barrier per chunk, warp-staggered ks, mid-chunk producer.
__device__ __forceinline__ void run_gemm(const float* const* aPtr,
                                         const float* __restrict__ Bp, int ldb,
                                         int nchunks, uint32_t* sm, Frag& fr) {
#pragma unroll
    for (int m = 0; m < 2; m++)
#pragma unroll
        for (int n = 0; n < 8; n++)
#pragma unroll
            for (int q = 0; q < 4; q++) fr.c[m][n][q] = 0.f;

    uint32_t sbase = (uint32_t)__cvta_generic_to_shared(sm);
    uint32_t stA[2] = { sbase, sbase + STAGE_FLOATS * 4u };
    uint32_t stB[2] = { sbase + TA_FLOATS * 4u, sbase + (STAGE_FLOATS + TA_FLOATS) * 4u };

    FragAddr fa = make_addr();
    int ks0 = (threadIdx.x >> 5) & 3;

    issue_chunk(aPtr, Bp, ldb, 0, stA[0], stB[0]);
    for (int c = 0; c < nchunks; c++) {
        asm volatile("cp.async.wait_group 0;" ::: "memory");
        __syncthreads();
        uint32_t sA = stA[c & 1], sB = stB[c & 1];
        compute_ks(sA, sB, fa, ks0, fr);
        if (c + 1 < nchunks)
            issue_chunk(aPtr, Bp, ldb, (c + 1) * KC, stA[(c + 1) & 1], stB[(c + 1) & 1]);
#pragma unroll
        for (int t = 1; t < 4; t++)
            compute_ks(sA, sB, fa, (ks0 + t) & 3, fr);
    }
}

// ---------------------------------------------------------------------------
// Kernel 0: per-batch prefix scan of sit_mask -> g_idx (compact->orig),
// g_rank (orig->compact), g_nc. Tail of g_idx filled with 0.
// ---------------------------------------------------------------------------
__global__ __launch_bounds__(256) void mask_scan_kernel(const float* __restrict__ mask) {
    int b = blockIdx.x, tid = threadIdx.x;
    const float* mr = mask + (size_t)b * T_;
    __shared__ int wsums[8];
    int base = tid * 8;
    int loc[8]; int cnt = 0;
#pragma unroll
    for (int k = 0; k < 8; k++) { loc[k] = cnt; cnt += (mr[base + k] != 0.f) ? 1 : 0; }
    int lane = tid & 31, wid = tid >> 5;
    int v = cnt;
#pragma unroll
    for (int o = 1; o < 32; o <<= 1) {
        int u = __shfl_up_sync(0xffffffffu, v, o);
        if (lane >= o) v += u;
    }
    if (lane == 31) wsums[wid] = v;
    __syncthreads();
    int woff = 0;
    for (int w = 0; w < wid; w++) woff += wsums[w];
    int excl = woff + v - cnt;
#pragma unroll
    for (int k = 0; k < 8; k++) {
        g_rank[b][base + k] = excl + loc[k];
        if (mr[base + k] != 0.f) g_idx[b][excl + loc[k]] = base + k;
    }
    __syncthreads();
    int total = 0;
#pragma unroll
    for (int w = 0; w < 8; w++) total += wsums[w];
    if (tid == 0) g_nc[b] = total;
    for (int ci = total + tid; ci < T_; ci += 256) g_idx[b][ci] = 0;
}

// ---------------------------------------------------------------------------
// Kernel 1: S[b,ci,j] = Xc[idx[ci],:].Xc[j,:] / sqrt(D), compact rows,
// ORIGINAL j (softmax denominator needs all j <= i).
// ---------------------------------------------------------------------------
__global__ void __launch_bounds__(128, 4) qk_mma_kernel() {
    int b = blockIdx.z;
    int nc = g_nc[b];
    int ci0 = blockIdx.y * 64;
    int j0 = blockIdx.x * 128;
    if (ci0 >= nc) return;
    int maxi = g_idx[b][min(ci0 + 63, nc - 1)];
    if (j0 > maxi) return;

    extern __shared__ uint32_t sm[];
    const float* Xb = g_Xc + (size_t)b * T_ * D_;
    int trow = threadIdx.x >> 3;
    const float* aPtr[4];
#pragma unroll
    for (int p = 0; p < 4; p++)
        aPtr[p] = Xb + (size_t)g_idx[b][ci0 + trow + p * 16] * D_;
    const float* Bp = Xb + (size_t)j0 * D_;

    Frag fr;
    run_gemm(aPtr, Bp, D_, D_ / KC, sm, fr);

    int tid = threadIdx.x, wid = tid >> 5, lane = tid & 31;
    int wr = (wid >> 1) * 32, wc = (wid & 1) * 64;
    int g = lane >> 2, tg = lane & 3;
    const float scl = 0.036084391824351615f;  // 1/sqrt(768)
    float* C = g_S + (size_t)b * T_ * T_;
#pragma unroll
    for (int m = 0; m < 2; m++) {
        int r0 = ci0 + wr + m * 16 + g;
#pragma unroll
        for (int n = 0; n < 8; n++) {
            int cc = j0 + wc + n * 8 + tg * 2;
            float2 v0 = make_float2(fr.c[m][n][0] * scl, fr.c[m][n][1] * scl);
            float2 v1 = make_float2(fr.c[m][n][2] * scl, fr.c[m][n][3] * scl);
            *(float2*)(C + (size_t)r0 * T_ + cc) = v0;
            *(float2*)(C + (size_t)(r0 + 8) * T_ + cc) = v1;
        }
    }
}

// ---------------------------------------------------------------------------
// Kernel 2: softmax on compact rows; max/sum over ORIGINAL j<=i (all terms),
// then writes weights in COMPACT-j space: w[cj] = exp(s[idx[cj]]-m)*inv for
// cj <= ci, 0 beyond, zero-filled to the pv tile bound.
// ---------------------------------------------------------------------------
__global__ __launch_bounds__(256) void softmax_kernel() {
    int b = blockIdx.x >> 11;
    int ci = blockIdx.x & (T_ - 1);
    int nc = g_nc[b];
    if (ci >= nc) return;
    int i = g_idx[b][ci];
    int kend = min((min((ci & ~63) + 63, nc - 1) + 128) & ~127, T_);
    float* srow = g_S + (size_t)b * T_ * T_ + (size_t)ci * T_;
    int tid = threadIdx.x;

    __shared__ float sh[T_];
    __shared__ float red[8];

    int n = i + 1;
    int n4 = n >> 2;
    int ntail = n4 * 4;

    float lm = -3.4e38f;
    for (int j4 = tid; j4 < n4; j4 += 256) {
        float4 v = ((const float4*)srow)[j4];
        ((float4*)sh)[j4] = v;
        lm = fmaxf(fmaxf(fmaxf(lm, v.x), fmaxf(v.y, v.z)), v.w);
    }
    for (int j = ntail + tid; j < n; j += 256) { float v = srow[j]; sh[j] = v; lm = fmaxf(lm, v); }
#pragma unroll
    for (int o = 16; o > 0; o >>= 1) lm = fmaxf(lm, __shfl_xor_sync(0xffffffffu, lm, o));
    if ((tid & 31) == 0) red[tid >> 5] = lm;
    __syncthreads();
    float m = red[0];
#pragma unroll
    for (int k = 1; k < 8; k++) m = fmaxf(m, red[k]);
    __syncthreads();

    float ls = 0.f;
    for (int j4 = tid; j4 < n4; j4 += 256) {
        float4 v = ((float4*)sh)[j4];
        v.x = __expf(v.x - m); v.y = __expf(v.y - m);
        v.z = __expf(v.z - m); v.w = __expf(v.w - m);
        ((float4*)sh)[j4] = v;
        ls += (v.x + v.y) + (v.z + v.w);
    }
    for (int j = ntail + tid; j < n; j += 256) { float e = __expf(sh[j] - m); sh[j] = e; ls += e; }
#pragma unroll
    for (int o = 16; o > 0; o >>= 1) ls += __shfl_xor_sync(0xffffffffu, ls, o);
    if ((tid & 31) == 0) red[tid >> 5] = ls;
    __syncthreads();
    float l = red[0];
#pragma unroll
    for (int k = 1; k < 8; k++) l += red[k];
    float inv = 1.0f / l;
    __syncthreads();

    // Compact-j weight write: causal test is simply cj <= ci (idx monotone,
    // compact columns are exactly the unmasked j's).
    const int4* idx4 = (const int4*)g_idx[b];
    for (int j4 = tid; j4 < kend / 4; j4 += 256) {
        int cjb = j4 * 4;
        int4 id = idx4[j4];
        float4 w;
        w.x = (cjb + 0 <= ci) ? sh[id.x] * inv : 0.f;
        w.y = (cjb + 1 <= ci) ? sh[id.y] * inv : 0.f;
        w.z = (cjb + 2 <= ci) ? sh[id.z] * inv : 0.f;
        w.w = (cjb + 3 <= ci) ? sh[id.w] * inv : 0.f;
        w.x = __uint_as_float(f2tf32(w.x));
        w.y = __uint_as_float(f2tf32(w.y));
        w.z = __uint_as_float(f2tf32(w.z));
        w.w = __uint_as_float(f2tf32(w.w));
        ((float4*)srow)[j4] = w;
    }
}

// ---------------------------------------------------------------------------
// Kernel 2.5: Xc = tf32(X); Xtc[d][rank(j)] = tf32(X[j][d]) for unmasked j;
// out concat half = X; masked rows: out[b,j,0:D] = 0.
// ---------------------------------------------------------------------------
__global__ __launch_bounds__(256) void transpose_concat_kernel(const float* __restrict__ X,
                                                               const float* __restrict__ mask,
                                                               float* __restrict__ out) {
    __shared__ float t[32][33];
    int b = blockIdx.z, j0 = blockIdx.x * 32, d0 = blockIdx.y * 32;
    int tx = threadIdx.x, ty = threadIdx.y;
    const float* Xb = X + (size_t)b * T_ * D_;
    float* Xc = g_Xc + (size_t)b * T_ * D_;
#pragma unroll
    for (int r = 0; r < 32; r += 8) {
        int j = j0 + ty + r;
        float v = Xb[(size_t)j * D_ + d0 + tx];
        float vt = __uint_as_float(f2tf32(v));
        t[ty + r][tx] = vt;
        float* orow = out + ((size_t)b * T_ + j) * (2 * D_);
        orow[D_ + d0 + tx] = v;
        if (mask[(size_t)b * T_ + j] == 0.f) orow[d0 + tx] = 0.f;
        Xc[(size_t)j * D_ + d0 + tx] = vt;
    }
    __syncthreads();
    // Column-compacted transpose: this thread owns orig column j0+tx.
    int jj = j0 + tx;
    int rk = g_rank[b][jj];
    bool um = (mask[(size_t)b * T_ + jj] != 0.f);
    float* Xtc = g_Xtc + (size_t)b * D_ * T_;
    if (um) {
#pragma unroll
        for (int r = 0; r < 32; r += 8)
            Xtc[(size_t)(d0 + ty + r) * T_ + rk] = t[tx][ty + r];
    }
}

// ---------------------------------------------------------------------------
// Kernel 3: out[b,idx[ci],d] = sum_{cj<=ci} W[ci,cj]*Xtc[d,cj] — fully compact
// GEMM, K = round_up(min(ci0+63,nc-1)+1, 128). Scatter epilogue, ci<nc guard.
// DESCENDING-K tile map.
// ---------------------------------------------------------------------------
__global__ void __launch_bounds__(128, 4) pv_mma_kernel(float* __restrict__ out) {
    int b = blockIdx.z;
    int nc = g_nc[b];
    int ci0 = (gridDim.y - 1 - blockIdx.y) * 64;
    int d0 = blockIdx.x * 128;
    if (ci0 >= nc) return;
    int kend = min((min(ci0 + 63, nc - 1) + 128) & ~127, T_);

    extern __shared__ uint32_t sm[];
    const float* Sb = g_S + (size_t)b * T_ * T_;
    int trow = threadIdx.x >> 3;
    const float* aPtr[4];
#pragma unroll
    for (int p = 0; p < 4; p++)
        aPtr[p] = Sb + (size_t)(ci0 + trow + p * 16) * T_;
    const float* Bp = g_Xtc + (size_t)b * D_ * T_ + (size_t)d0 * T_;

    Frag fr;
    run_gemm(aPtr, Bp, T_, kend / KC, sm, fr);

    int tid = threadIdx.x, wid = tid >> 5, lane = tid & 31;
    int wr = (wid >> 1) * 32, wc = (wid & 1) * 64;
    int g = lane >> 2, tg = lane & 3;
#pragma unroll
    for (int m = 0; m < 2; m++) {
        int rc = ci0 + wr + m * 16 + g;
        int io0 = (rc < nc) ? g_idx[b][rc] : -1;
        int io1 = (rc + 8 < nc) ? g_idx[b][rc + 8] : -1;
        float* o0 = out + ((size_t)b * T_ + io0) * (2 * D_) + d0;
        float* o1 = out + ((size_t)b * T_ + io1) * (2 * D_) + d0;
#pragma unroll
        for (int n = 0; n < 8; n++) {
            int cc = wc + n * 8 + tg * 2;
            if (io0 >= 0) *(float2*)(o0 + cc) = make_float2(fr.c[m][n][0], fr.c[m][n][1]);
            if (io1 >= 0) *(float2*)(o1 + cc) = make_float2(fr.c[m][n][2], fr.c[m][n][3]);
        }
    }
}

extern "C" void kernel_launch(void* const* d_in, const int* in_sizes, int n_in,
                              void* d_out, int out_size) {
    const float* X = (const float*)d_in[0];
    const float* mask = (const float*)d_in[1];
    // d_in[2] (proposition_matrix) is unused by the reference computation.
    float* out = (float*)d_out;

    cudaFuncSetAttribute(qk_mma_kernel, cudaFuncAttributeMaxDynamicSharedMemorySize, SMEM_DYN);
    cudaFuncSetAttribute(pv_mma_kernel, cudaFuncAttributeMaxDynamicSharedMemorySize, SMEM_DYN);

    mask_scan_kernel<<<B_, 256>>>(mask);

    dim3 gt(T_ / 32, D_ / 32, B_);
    transpose_concat_kernel<<<gt, dim3(32, 8)>>>(X, mask, out);

    dim3 g1(T_ / 128, T_ / 64, B_);
    qk_mma_kernel<<<g1, 128, SMEM_DYN>>>();

    softmax_kernel<<<B_ * T_, 256>>>();

    dim3 g3(D_ / 128, T_ / 64, B_);
    pv_mma_kernel<<<g3, 128, SMEM_DYN>>>(out);
}